// round 3
// baseline (speedup 1.0000x reference)
#include <cuda_runtime.h>
#include <cstdint>

// CRF forward log-partition. B=512, T=1024, L=64.
// One warp per batch; probability-domain recurrence:
//   p_{t+1} = (E @ p_t) .* exp(logit_t),  E = exp(trans) in registers.
// Exact power-of-2 rescale every 4 steps, DEFERRED: the 2^-k scale is folded
// into the next step's exp(logit) so REDUX/scale never sit on the
// inter-step critical path.
// logZ = ktot*ln2 + log( pend * sum_j p[j] * exp(trans[63,j]) ).

#define CRF_B 512
#define CRF_T 1024
#define CRF_L 64
#define C_LOG2E 1.4426950408889634f
#define C_LN2   0.6931471805599453f

using u64 = unsigned long long;

__device__ __forceinline__ float ex2f(float x) {
    float r; asm("ex2.approx.f32 %0, %1;" : "=f"(r) : "f"(x)); return r;
}
__device__ __forceinline__ u64 packf2(float lo, float hi) {
    u64 r; asm("mov.b64 %0, {%1, %2};" : "=l"(r) : "f"(lo), "f"(hi)); return r;
}
__device__ __forceinline__ void unpackf2(u64 v, float& lo, float& hi) {
    asm("mov.b64 {%0, %1}, %2;" : "=f"(lo), "=f"(hi) : "l"(v));
}
#define FMA2(acc, a, b) \
    asm("fma.rn.f32x2 %0, %1, %2, %0;" : "+l"(acc) : "l"(a), "l"(b))
#define ADD2(acc, a) \
    asm("add.rn.f32x2 %0, %0, %1;" : "+l"(acc) : "l"(a))

__device__ __forceinline__ float2 eexp(float2 lg) {
    return make_float2(ex2f(lg.x * C_LOG2E), ex2f(lg.y * C_LOG2E));
}

// One CRF step. Reads all 64 p values from sp_r (32x LDS.64 broadcast, the
// R1 codegen pattern), writes this lane's new pair to sp_w.
// el = precomputed exp(logit) pair; pend = deferred power-of-2 rescale from
// the previous rescale step (exactly 1.0 otherwise).
template <bool RESCALE>
__device__ __forceinline__ void crf_step(
    float2 el,
    const u64 (&Ea)[32], const u64 (&Eb)[32],
    const float2* __restrict__ sp_r,
    u64* __restrict__ sp_w,
    int lane, int& ktot, float& pend)
{
    // Apply deferred scale (off critical path: pend & el known at entry).
    el.x *= pend;
    el.y *= pend;

    u64 a[4] = {0ull, 0ull, 0ull, 0ull};
    u64 b[4] = {0ull, 0ull, 0ull, 0ull};
#pragma unroll
    for (int jj = 0; jj < 32; jj++) {
        u64 p = *reinterpret_cast<const u64*>(sp_r + jj);   // LDS.64 broadcast
        FMA2(a[jj & 3], Ea[jj], p);
        FMA2(b[jj & 3], Eb[jj], p);
    }
    ADD2(a[0], a[1]); ADD2(a[2], a[3]); ADD2(a[0], a[2]);
    ADD2(b[0], b[1]); ADD2(b[2], b[3]); ADD2(b[0], b[2]);
    float ax, ay, bx, by;
    unpackf2(a[0], ax, ay);
    unpackf2(b[0], bx, by);
    float pA = (ax + ay) * el.x;           // new p[2*lane]
    float pB = (bx + by) * el.y;           // new p[2*lane+1]

    sp_w[lane] = packf2(pA, pB);           // store FIRST (unrescaled)

    if (RESCALE) {
        // Runs after the store; result only needed ~60cyc into next step.
        float m = fmaxf(pA, pB);           // p > 0: uint cmp == float cmp
        unsigned mu = __reduce_max_sync(0xffffffffu, __float_as_uint(m));
        int k = (int)(mu >> 23) - 127;
        ktot += k;
        pend = __int_as_float((127 - k) << 23);   // exact 2^-k
    } else {
        pend = 1.0f;
    }
    __syncwarp();
}

__global__ void __launch_bounds__(128)
crf_fwd_kernel(const float* __restrict__ logits,
               const int*   __restrict__ lens,
               const float* __restrict__ trans,
               float*       __restrict__ out)
{
    __shared__ __align__(16) float2 sp[4][2][32];   // [warp][buffer][pair]

    const int w    = threadIdx.x >> 5;
    const int lane = threadIdx.x & 31;
    const int b    = blockIdx.x * 4 + w;            // grid=128 -> b < 512

    const float2* rd0 = sp[w][0];
    const float2* rd1 = sp[w][1];
    u64* wr0 = reinterpret_cast<u64*>(sp[w][0]);
    u64* wr1 = reinterpret_cast<u64*>(sp[w][1]);

    // ---- E = exp(trans), rows 2*lane and 2*lane+1, packed f32x2 ----
    u64 Ea[32], Eb[32];
    const float* ra = trans + (2 * lane)     * CRF_L;
    const float* rb = trans + (2 * lane + 1) * CRF_L;
#pragma unroll
    for (int jj = 0; jj < 32; jj++) {
        Ea[jj] = packf2(expf(ra[2 * jj]), expf(ra[2 * jj + 1]));
        Eb[jj] = packf2(expf(rb[2 * jj]), expf(rb[2 * jj + 1]));
    }
    const float2 e63 = make_float2(expf(trans[63 * CRF_L + 2 * lane]),
                                   expf(trans[63 * CRF_L + 2 * lane + 1]));

    // ---- init: delta at start label 62 ----
    wr0[lane] = packf2((2 * lane == 62) ? 1.0f : 0.0f,
                       (2 * lane + 1 == 62) ? 1.0f : 0.0f);
    __syncwarp();

    int   ktot = 0;
    float pend = 1.0f;
    const int len = lens[b];

    const float2* lgp =
        reinterpret_cast<const float2*>(logits + (size_t)b * CRF_T * CRF_L) + lane;

    // 4-deep prefetch with exp(logit) precomputed off the critical path.
    float2 e0, e1, e2, e3;
    if (len > 0) e0 = eexp(__ldg(lgp));
    if (len > 1) e1 = eexp(__ldg(lgp + 32));
    if (len > 2) e2 = eexp(__ldg(lgp + 64));
    if (len > 3) e3 = eexp(__ldg(lgp + 96));

    int t = 0;
    for (; t + 4 <= len; t += 4) {       // p in buffer 0 at loop top
        float2 g;
        g = e0; if (t + 4 < len) e0 = eexp(__ldg(lgp + (size_t)(t + 4) * 32));
        crf_step<false>(g, Ea, Eb, rd0, wr1, lane, ktot, pend);
        g = e1; if (t + 5 < len) e1 = eexp(__ldg(lgp + (size_t)(t + 5) * 32));
        crf_step<false>(g, Ea, Eb, rd1, wr0, lane, ktot, pend);
        g = e2; if (t + 6 < len) e2 = eexp(__ldg(lgp + (size_t)(t + 6) * 32));
        crf_step<false>(g, Ea, Eb, rd0, wr1, lane, ktot, pend);
        g = e3; if (t + 7 < len) e3 = eexp(__ldg(lgp + (size_t)(t + 7) * 32));
        crf_step<true >(g, Ea, Eb, rd1, wr0, lane, ktot, pend);
    }

    int buf = 0;
    for (; t < len; ++t) {               // <=3 remainder steps
        float2 g = eexp(__ldg(lgp + (size_t)t * 32));
        if (buf == 0) crf_step<false>(g, Ea, Eb, rd0, wr1, lane, ktot, pend);
        else          crf_step<false>(g, Ea, Eb, rd1, wr0, lane, ktot, pend);
        buf ^= 1;
    }

    // ---- finalize: logZ = ktot*ln2 + log( pend * sum_j p[j]*E[63,j] ) ----
    float px, py;
    unpackf2((buf == 0 ? wr0 : wr1)[lane], px, py);
    float part = e63.x * px + e63.y * py;
#pragma unroll
    for (int o = 16; o > 0; o >>= 1)
        part += __shfl_xor_sync(0xffffffffu, part, o);
    if (lane == 0)
        out[b] = (float)ktot * C_LN2 + __logf(part * pend);
}

extern "C" void kernel_launch(void* const* d_in, const int* in_sizes, int n_in,
                              void* d_out, int out_size)
{
    const float* logits = (const float*)d_in[0];   // [512,1024,64] f32
    const int*   lens   = (const int*)  d_in[1];   // [512] i32
    const float* trans  = (const float*)d_in[2];   // [64,64] f32
    float* out = (float*)d_out;                    // [512] f32

    crf_fwd_kernel<<<CRF_B / 4, 128>>>(logits, lens, trans, out);
}

// round 4
// speedup vs baseline: 1.7060x; 1.7060x over previous
#include <cuda_runtime.h>
#include <cstdint>

// CRF forward log-partition. B=512, T=1024, L=64.
// TWO batches per warp (b, b+256) advanced in lockstep sharing the register-
// resident E = exp(trans); the second chain's FMAs fill the first chain's
// LDS/store/sync stall cycles. Probability-domain recurrence:
//   p_{t+1} = (E @ p_t) .* exp(logit_t)
// Exact power-of-2 rescale every 4 steps, deferred (folded into next el).
// logZ = ktot*ln2 + log( pend * sum_j p[j] * exp(trans[63,j]) ).

#define CRF_B 512
#define CRF_T 1024
#define CRF_L 64
#define C_LOG2E 1.4426950408889634f
#define C_LN2   0.6931471805599453f

using u64 = unsigned long long;

__device__ __forceinline__ float ex2f(float x) {
    float r; asm("ex2.approx.f32 %0, %1;" : "=f"(r) : "f"(x)); return r;
}
__device__ __forceinline__ u64 packf2(float lo, float hi) {
    u64 r; asm("mov.b64 %0, {%1, %2};" : "=l"(r) : "f"(lo), "f"(hi)); return r;
}
__device__ __forceinline__ void unpackf2(u64 v, float& lo, float& hi) {
    asm("mov.b64 {%0, %1}, %2;" : "=f"(lo), "=f"(hi) : "l"(v));
}
#define FMA2(acc, a, b) \
    asm("fma.rn.f32x2 %0, %1, %2, %0;" : "+l"(acc) : "l"(a), "l"(b))
#define ADD2(acc, a) \
    asm("add.rn.f32x2 %0, %0, %1;" : "+l"(acc) : "l"(a))

__device__ __forceinline__ float2 eexp(float2 lg) {
    return make_float2(ex2f(lg.x * C_LOG2E), ex2f(lg.y * C_LOG2E));
}

// One lockstep step for two batches. Inner loop keeps R1's exact idiom:
// paired LDS.64 loads + scalar named accumulators (this is the shape ptxas
// front-batches; the R2/R3 rotated-array variant serialized to MLP=1).
template <bool RESCALE>
__device__ __forceinline__ void crf_step2(
    float2 elA, float2 elB,
    const u64 (&Ea)[32], const u64 (&Eb)[32],
    const float2* __restrict__ rdA, u64* __restrict__ wrA,
    const float2* __restrict__ rdB, u64* __restrict__ wrB,
    int lane, bool actA, bool actB,
    int& ktotA, float& pendA, int& ktotB, float& pendB)
{
    // Apply deferred power-of-2 scale (operands ready at entry -> off path).
    elA.x *= pendA; elA.y *= pendA;
    elB.x *= pendB; elB.y *= pendB;

    u64 aA0 = 0ull, aA1 = 0ull, bA0 = 0ull, bA1 = 0ull;
    u64 aB0 = 0ull, aB1 = 0ull, bB0 = 0ull, bB1 = 0ull;
#pragma unroll
    for (int jj = 0; jj < 32; jj += 2) {
        u64 pA0 = *reinterpret_cast<const u64*>(rdA + jj);
        u64 pA1 = *reinterpret_cast<const u64*>(rdA + jj + 1);
        u64 pB0 = *reinterpret_cast<const u64*>(rdB + jj);
        u64 pB1 = *reinterpret_cast<const u64*>(rdB + jj + 1);
        FMA2(aA0, Ea[jj],     pA0);
        FMA2(bA0, Eb[jj],     pA0);
        FMA2(aA1, Ea[jj + 1], pA1);
        FMA2(bA1, Eb[jj + 1], pA1);
        FMA2(aB0, Ea[jj],     pB0);
        FMA2(bB0, Eb[jj],     pB0);
        FMA2(aB1, Ea[jj + 1], pB1);
        FMA2(bB1, Eb[jj + 1], pB1);
    }
    ADD2(aA0, aA1); ADD2(bA0, bA1);
    ADD2(aB0, aB1); ADD2(bB0, bB1);
    float ax, ay, bx, by;

    unpackf2(aA0, ax, ay);
    unpackf2(bA0, bx, by);
    float pAx = (ax + ay) * elA.x;
    float pAy = (bx + by) * elA.y;

    unpackf2(aB0, ax, ay);
    unpackf2(bB0, bx, by);
    float pBx = (ax + ay) * elB.x;
    float pBy = (bx + by) * elB.y;

    if (actA) wrA[lane] = packf2(pAx, pAy);   // store first (unrescaled)
    if (actB) wrB[lane] = packf2(pBx, pBy);

    if (RESCALE) {
        unsigned muA = __reduce_max_sync(0xffffffffu,
                           __float_as_uint(fmaxf(pAx, pAy)));
        unsigned muB = __reduce_max_sync(0xffffffffu,
                           __float_as_uint(fmaxf(pBx, pBy)));
        int kA = (int)(muA >> 23) - 127;
        int kB = (int)(muB >> 23) - 127;
        if (actA) { ktotA += kA; pendA = __int_as_float((127 - kA) << 23); }
        if (actB) { ktotB += kB; pendB = __int_as_float((127 - kB) << 23); }
    } else {
        if (actA) pendA = 1.0f;
        if (actB) pendB = 1.0f;
    }
    __syncwarp();
}

__global__ void __launch_bounds__(128, 1)
crf_fwd_kernel(const float* __restrict__ logits,
               const int*   __restrict__ lens,
               const float* __restrict__ trans,
               float*       __restrict__ out)
{
    __shared__ __align__(16) float2 sp[4][2][2][32]; // [warp][batch][buf][pair]

    const int w    = threadIdx.x >> 5;
    const int lane = threadIdx.x & 31;
    const int bA   = blockIdx.x * 4 + w;             // grid=64 -> bA < 256
    const int bB   = bA + 256;

    const float2* rdA0 = sp[w][0][0];  const float2* rdA1 = sp[w][0][1];
    const float2* rdB0 = sp[w][1][0];  const float2* rdB1 = sp[w][1][1];
    u64* wrA0 = reinterpret_cast<u64*>(sp[w][0][0]);
    u64* wrA1 = reinterpret_cast<u64*>(sp[w][0][1]);
    u64* wrB0 = reinterpret_cast<u64*>(sp[w][1][0]);
    u64* wrB1 = reinterpret_cast<u64*>(sp[w][1][1]);

    // ---- E = exp(trans), rows 2*lane and 2*lane+1, packed f32x2 ----
    u64 Ea[32], Eb[32];
    const float* ra = trans + (2 * lane)     * CRF_L;
    const float* rb = trans + (2 * lane + 1) * CRF_L;
#pragma unroll
    for (int jj = 0; jj < 32; jj++) {
        Ea[jj] = packf2(expf(ra[2 * jj]), expf(ra[2 * jj + 1]));
        Eb[jj] = packf2(expf(rb[2 * jj]), expf(rb[2 * jj + 1]));
    }
    const float2 e63 = make_float2(expf(trans[63 * CRF_L + 2 * lane]),
                                   expf(trans[63 * CRF_L + 2 * lane + 1]));

    // ---- init: delta at start label 62 ----
    u64 p0 = packf2((2 * lane == 62) ? 1.0f : 0.0f,
                    (2 * lane + 1 == 62) ? 1.0f : 0.0f);
    wrA0[lane] = p0;
    wrB0[lane] = p0;
    __syncwarp();

    int   ktotA = 0, ktotB = 0;
    float pendA = 1.0f, pendB = 1.0f;
    const int lenA = lens[bA];
    const int lenB = lens[bB];
    const int tmax = max(lenA, lenB);

    const float2* lgA =
        reinterpret_cast<const float2*>(logits + (size_t)bA * CRF_T * CRF_L) + lane;
    const float2* lgB =
        reinterpret_cast<const float2*>(logits + (size_t)bB * CRF_T * CRF_L) + lane;

    // 4-deep prefetch per batch, exp() applied off the critical path.
    float2 eA0, eA1, eA2, eA3, eB0, eB1, eB2, eB3;
    if (lenA > 0) eA0 = eexp(__ldg(lgA));
    if (lenA > 1) eA1 = eexp(__ldg(lgA + 32));
    if (lenA > 2) eA2 = eexp(__ldg(lgA + 64));
    if (lenA > 3) eA3 = eexp(__ldg(lgA + 96));
    if (lenB > 0) eB0 = eexp(__ldg(lgB));
    if (lenB > 1) eB1 = eexp(__ldg(lgB + 32));
    if (lenB > 2) eB2 = eexp(__ldg(lgB + 64));
    if (lenB > 3) eB3 = eexp(__ldg(lgB + 96));

    int t = 0;
    for (; t + 4 <= tmax; t += 4) {      // p in buffer 0 at loop top
        float2 gA, gB;
        gA = eA0; if (t + 4 < lenA) eA0 = eexp(__ldg(lgA + (size_t)(t + 4) * 32));
        gB = eB0; if (t + 4 < lenB) eB0 = eexp(__ldg(lgB + (size_t)(t + 4) * 32));
        crf_step2<false>(gA, gB, Ea, Eb, rdA0, wrA1, rdB0, wrB1, lane,
                         t + 0 < lenA, t + 0 < lenB, ktotA, pendA, ktotB, pendB);
        gA = eA1; if (t + 5 < lenA) eA1 = eexp(__ldg(lgA + (size_t)(t + 5) * 32));
        gB = eB1; if (t + 5 < lenB) eB1 = eexp(__ldg(lgB + (size_t)(t + 5) * 32));
        crf_step2<false>(gA, gB, Ea, Eb, rdA1, wrA0, rdB1, wrB0, lane,
                         t + 1 < lenA, t + 1 < lenB, ktotA, pendA, ktotB, pendB);
        gA = eA2; if (t + 6 < lenA) eA2 = eexp(__ldg(lgA + (size_t)(t + 6) * 32));
        gB = eB2; if (t + 6 < lenB) eB2 = eexp(__ldg(lgB + (size_t)(t + 6) * 32));
        crf_step2<false>(gA, gB, Ea, Eb, rdA0, wrA1, rdB0, wrB1, lane,
                         t + 2 < lenA, t + 2 < lenB, ktotA, pendA, ktotB, pendB);
        gA = eA3; if (t + 7 < lenA) eA3 = eexp(__ldg(lgA + (size_t)(t + 7) * 32));
        gB = eB3; if (t + 7 < lenB) eB3 = eexp(__ldg(lgB + (size_t)(t + 7) * 32));
        crf_step2<true >(gA, gB, Ea, Eb, rdA1, wrA0, rdB1, wrB0, lane,
                         t + 3 < lenA, t + 3 < lenB, ktotA, pendA, ktotB, pendB);
    }

    int buf = 0;
    for (; t < tmax; ++t) {              // <=3 remainder steps
        float2 gA = make_float2(1.0f, 1.0f), gB = gA;
        if (t < lenA) gA = eexp(__ldg(lgA + (size_t)t * 32));
        if (t < lenB) gB = eexp(__ldg(lgB + (size_t)t * 32));
        if (buf == 0)
            crf_step2<false>(gA, gB, Ea, Eb, rdA0, wrA1, rdB0, wrB1, lane,
                             t < lenA, t < lenB, ktotA, pendA, ktotB, pendB);
        else
            crf_step2<false>(gA, gB, Ea, Eb, rdA1, wrA0, rdB1, wrB0, lane,
                             t < lenA, t < lenB, ktotA, pendA, ktotB, pendB);
        buf ^= 1;
    }

    // ---- finalize: logZ = ktot*ln2 + log( pend * sum_j p[j]*E[63,j] ) ----
    float px, py;
    unpackf2((lenA & 1 ? wrA1 : wrA0)[lane], px, py);
    float partA = e63.x * px + e63.y * py;
    unpackf2((lenB & 1 ? wrB1 : wrB0)[lane], px, py);
    float partB = e63.x * px + e63.y * py;
#pragma unroll
    for (int o = 16; o > 0; o >>= 1) {
        partA += __shfl_xor_sync(0xffffffffu, partA, o);
        partB += __shfl_xor_sync(0xffffffffu, partB, o);
    }
    if (lane == 0) {
        out[bA] = (float)ktotA * C_LN2 + __logf(partA * pendA);
        out[bB] = (float)ktotB * C_LN2 + __logf(partB * pendB);
    }
}

extern "C" void kernel_launch(void* const* d_in, const int* in_sizes, int n_in,
                              void* d_out, int out_size)
{
    const float* logits = (const float*)d_in[0];   // [512,1024,64] f32
    const int*   lens   = (const int*)  d_in[1];   // [512] i32
    const float* trans  = (const float*)d_in[2];   // [64,64] f32
    float* out = (float*)d_out;                    // [512] f32

    crf_fwd_kernel<<<CRF_B / 8, 128>>>(logits, lens, trans, out);
}

// round 5
// speedup vs baseline: 2.2586x; 1.3239x over previous
#include <cuda_runtime.h>
#include <cstdint>

// CRF forward log-partition. B=512, T=1024, L=64.
// One 64-thread CTA per batch; lane i owns output row i.
// Probability-domain recurrence: p_{t+1} = (E @ p_t) .* exp(logit_t),
// E = exp(trans) register-resident (32 packed f32x2 per lane).
// Exact power-of-2 rescale every 4 steps, deferred: rescale step records the
// max exponent (per-warp REDUX -> smax[2]); the next group-start folds 2^-k
// into its exp(logit). Nothing heavy sits on the inter-step critical path.
// logZ = ktot*ln2 + log( sum_j p[j] * exp(trans[63,j]) ).

#define CRF_B 512
#define CRF_T 1024
#define CRF_L 64
#define C_LOG2E 1.4426950408889634f
#define C_LN2   0.6931471805599453f

using u64 = unsigned long long;

__device__ __forceinline__ float ex2f(float x) {
    float r; asm("ex2.approx.f32 %0, %1;" : "=f"(r) : "f"(x)); return r;
}
__device__ __forceinline__ u64 packf2(float lo, float hi) {
    u64 r; asm("mov.b64 %0, {%1, %2};" : "=l"(r) : "f"(lo), "f"(hi)); return r;
}
__device__ __forceinline__ void unpackf2(u64 v, float& lo, float& hi) {
    asm("mov.b64 {%0, %1}, %2;" : "=f"(lo), "=f"(hi) : "l"(v));
}
#define FMA2(acc, a, b) \
    asm("fma.rn.f32x2 %0, %1, %2, %0;" : "+l"(acc) : "l"(a), "l"(b))
#define ADD2(acc, a) \
    asm("add.rn.f32x2 %0, %0, %1;" : "+l"(acc) : "l"(a))

// One CRF step. rd/wr are the 64-float p buffers (double-buffered).
// FOLD: apply the deferred 2^-k rescale recorded in smax (group starts).
// RESCALE: record max exponent of new p into smax (4th step of a group).
template <bool FOLD, bool RESCALE>
__device__ __forceinline__ void crf_step(
    float el, const u64 (&E)[32],
    const float* __restrict__ rd, float* __restrict__ wr,
    float* __restrict__ smax, int tid, int& ktot)
{
    if (FOLD) {
        float m = fmaxf(smax[0], smax[1]);          // m > 0
        int k = (__float_as_int(m) >> 23) - 127;
        ktot += k;
        el *= __int_as_float((127 - k) << 23);      // exact 2^-k
    }

    const u64* pr = reinterpret_cast<const u64*>(rd);
    u64 c0 = 0ull, c1 = 0ull, c2 = 0ull, c3 = 0ull;
#pragma unroll
    for (int jj = 0; jj < 32; jj += 4) {            // R1 idiom: paired LDS.64
        u64 p0 = pr[jj];                            // + named scalar accums
        u64 p1 = pr[jj + 1];
        u64 p2 = pr[jj + 2];
        u64 p3 = pr[jj + 3];
        FMA2(c0, E[jj],     p0);
        FMA2(c1, E[jj + 1], p1);
        FMA2(c2, E[jj + 2], p2);
        FMA2(c3, E[jj + 3], p3);
    }
    ADD2(c0, c1); ADD2(c2, c3); ADD2(c0, c2);
    float ev, od;
    unpackf2(c0, ev, od);
    float pn = (ev + od) * el;                      // new p[tid]

    wr[tid] = pn;                                   // store FIRST (unrescaled)

    if (RESCALE) {                                  // off the critical path
        unsigned mu = __reduce_max_sync(0xffffffffu, __float_as_uint(pn));
        if ((tid & 31) == 0) smax[tid >> 5] = __uint_as_float(mu);
    }
    __syncthreads();                                // nw=2: ~7cyc floor
}

__global__ void __launch_bounds__(64)
crf_fwd_kernel(const float* __restrict__ logits,
               const int*   __restrict__ lens,
               const float* __restrict__ trans,
               float*       __restrict__ out)
{
    __shared__ __align__(16) float p[2][CRF_L];
    __shared__ float smax[2];
    __shared__ float ws[2];

    const int tid = threadIdx.x;                    // 0..63 == output row
    const int b   = blockIdx.x;

    // ---- E row tid = exp(trans[tid, :]), packed f32x2 over j-pairs ----
    u64 E[32];
    const float* row = trans + tid * CRF_L;
#pragma unroll
    for (int jj = 0; jj < 32; jj++)
        E[jj] = packf2(expf(row[2 * jj]), expf(row[2 * jj + 1]));
    const float e63 = expf(trans[63 * CRF_L + tid]);

    // ---- init: delta at start label 62; smax=1.0 -> first fold is k=0 ----
    p[0][tid] = (tid == 62) ? 1.0f : 0.0f;
    if (tid < 2) smax[tid] = 1.0f;

    int ktot = 0;
    const int len = lens[b];
    const float* lg = logits + (size_t)b * CRF_T * CRF_L + tid;

    // 4-deep prefetch; exp() precomputed off the critical path.
    float e0, e1, e2, e3;
    if (len > 0) e0 = ex2f(__ldg(lg)                    * C_LOG2E);
    if (len > 1) e1 = ex2f(__ldg(lg + 1 * CRF_L)        * C_LOG2E);
    if (len > 2) e2 = ex2f(__ldg(lg + 2 * CRF_L)        * C_LOG2E);
    if (len > 3) e3 = ex2f(__ldg(lg + 3 * CRF_L)        * C_LOG2E);
    __syncthreads();

    int t = 0;
    for (; t + 4 <= len; t += 4) {                  // p in buffer 0 at top
        float g;
        g = e0; if (t + 4 < len) e0 = ex2f(__ldg(lg + (size_t)(t + 4) * CRF_L) * C_LOG2E);
        crf_step<true,  false>(g, E, p[0], p[1], smax, tid, ktot);
        g = e1; if (t + 5 < len) e1 = ex2f(__ldg(lg + (size_t)(t + 5) * CRF_L) * C_LOG2E);
        crf_step<false, false>(g, E, p[1], p[0], smax, tid, ktot);
        g = e2; if (t + 6 < len) e2 = ex2f(__ldg(lg + (size_t)(t + 6) * CRF_L) * C_LOG2E);
        crf_step<false, false>(g, E, p[0], p[1], smax, tid, ktot);
        g = e3; if (t + 7 < len) e3 = ex2f(__ldg(lg + (size_t)(t + 7) * CRF_L) * C_LOG2E);
        crf_step<false, true >(g, E, p[1], p[0], smax, tid, ktot);
    }

    // remainder: t % 4 == 0 entering; fold pending rescale on first step.
    if (t < len) {
        crf_step<true, false>(e0, E, p[0], p[1], smax, tid, ktot); t++;
        if (t < len) { crf_step<false, false>(e1, E, p[1], p[0], smax, tid, ktot); t++; }
        if (t < len) { crf_step<false, false>(e2, E, p[0], p[1], smax, tid, ktot); t++; }
    }

    // ---- finalize: logZ = ktot*ln2 + log( sum_j p[j]*E[63,j] ) ----
    // (an un-folded trailing rescale only recorded smax; p itself is unscaled)
    float pf = p[len & 1][tid];
    float part = e63 * pf;
#pragma unroll
    for (int o = 16; o > 0; o >>= 1)
        part += __shfl_xor_sync(0xffffffffu, part, o);
    if ((tid & 31) == 0) ws[tid >> 5] = part;
    __syncthreads();
    if (tid == 0)
        out[b] = (float)ktot * C_LN2 + __logf(ws[0] + ws[1]);
}

extern "C" void kernel_launch(void* const* d_in, const int* in_sizes, int n_in,
                              void* d_out, int out_size)
{
    const float* logits = (const float*)d_in[0];   // [512,1024,64] f32
    const int*   lens   = (const int*)  d_in[1];   // [512] i32
    const float* trans  = (const float*)d_in[2];   // [64,64] f32
    float* out = (float*)d_out;                    // [512] f32

    crf_fwd_kernel<<<CRF_B, 64>>>(logits, lens, trans, out);
}